// round 7
// baseline (speedup 1.0000x reference)
#include <cuda_runtime.h>
#include <cstdint>

// InfoNCE loss, N=16384, D=128, T=0.07
//   K1: normalize (fp32), exact diag, store tf32-rounded normalized vectors
//   K2: 128x128-tile NT-GEMM on tensor cores (mma.sync tf32) fused with
//       streaming sum of exp((dot-1)/T) per row   [logits <= 1/T since cos<=1]
//   K3: loss = mean(log(rowsum) + 1/T - diag)

#define NN 16384
#define DD 128
#define INV_T 14.285714285714286f
#define C2EXP 20.6108932233901f      // INV_T / ln(2):  exp((d-1)/T) = 2^(d*C2 - C2)

#define BM 128
#define BN 128
#define LDSW 132              // row stride in floats (128+4 pad -> conflict-free frags)
#define NT (NN / BN)          // 128 column tiles

__device__ float g_an[NN * DD];
__device__ float g_pn[NN * DD];
__device__ float g_diag[NN];
__device__ float g_rows[NN];

// ---------------------------------------------------------------------------
__device__ __forceinline__ float tf32_rna(float x) {
    uint32_t u;
    asm("cvt.rna.tf32.f32 %0, %1;" : "=r"(u) : "f"(x));
    return __uint_as_float(u);
}

__device__ __forceinline__ float ex2(float x) {
    float y;
    asm("ex2.approx.ftz.f32 %0, %1;" : "=f"(y) : "f"(x));
    return y;
}

#define CP_ASYNC16(dst_u32, src_ptr) \
    asm volatile("cp.async.cg.shared.global [%0], [%1], 16;" :: "r"(dst_u32), "l"(src_ptr))
#define CP_COMMIT() asm volatile("cp.async.commit_group;")
#define CP_WAIT1()  asm volatile("cp.async.wait_group 1;")

__device__ __forceinline__ void mma_tf32(float c[4], const uint32_t a[4],
                                         const uint32_t b[2]) {
    asm volatile(
        "mma.sync.aligned.m16n8k8.row.col.f32.tf32.tf32.f32 "
        "{%0,%1,%2,%3}, {%4,%5,%6,%7}, {%8,%9}, {%0,%1,%2,%3};\n"
        : "+f"(c[0]), "+f"(c[1]), "+f"(c[2]), "+f"(c[3])
        : "r"(a[0]), "r"(a[1]), "r"(a[2]), "r"(a[3]), "r"(b[0]), "r"(b[1]));
}

// ---------------------------------------------------------------------------
// K1: normalize + exact diagonal; outputs are tf32-rounded (rna).
// ---------------------------------------------------------------------------
__global__ void __launch_bounds__(256) normalize_kernel(
    const float* __restrict__ A, const float* __restrict__ P) {
    int warp = threadIdx.x >> 5;
    int lane = threadIdx.x & 31;
    int row  = blockIdx.x * 8 + warp;

    float4 a = ((const float4*)(A + (size_t)row * DD))[lane];
    float4 p = ((const float4*)(P + (size_t)row * DD))[lane];

    float sa = a.x * a.x + a.y * a.y + a.z * a.z + a.w * a.w;
    float sp = p.x * p.x + p.y * p.y + p.z * p.z + p.w * p.w;
    #pragma unroll
    for (int o = 16; o > 0; o >>= 1) {
        sa += __shfl_xor_sync(0xFFFFFFFFu, sa, o);
        sp += __shfl_xor_sync(0xFFFFFFFFu, sp, o);
    }
    float ra = 1.0f / fmaxf(sqrtf(sa), 1e-12f);
    float rp = 1.0f / fmaxf(sqrtf(sp), 1e-12f);

    a.x *= ra; a.y *= ra; a.z *= ra; a.w *= ra;
    p.x *= rp; p.y *= rp; p.z *= rp; p.w *= rp;

    // exact fp32 diagonal BEFORE tf32 rounding
    float dot = a.x * p.x + a.y * p.y + a.z * p.z + a.w * p.w;
    #pragma unroll
    for (int o = 16; o > 0; o >>= 1)
        dot += __shfl_xor_sync(0xFFFFFFFFu, dot, o);
    if (lane == 0) g_diag[row] = dot * INV_T;

    float4 ar = make_float4(tf32_rna(a.x), tf32_rna(a.y), tf32_rna(a.z), tf32_rna(a.w));
    float4 pr = make_float4(tf32_rna(p.x), tf32_rna(p.y), tf32_rna(p.z), tf32_rna(p.w));
    ((float4*)(g_an + (size_t)row * DD))[lane] = ar;
    ((float4*)(g_pn + (size_t)row * DD))[lane] = pr;
}

// ---------------------------------------------------------------------------
// K2: tensor-core GEMM + fused streaming exp-sum.
// 256 threads = 8 warps, warp grid 2(M) x 4(N); warp tile 64x32 of C.
// Tiles stored row-major [m|n][k] with stride LDSW:
//   fragment LDS addr = r*LDSW + k  ->  bank = (4*group + tig) + const : CF.
// A tile resident; B tile double-buffered via cp.async.
// ---------------------------------------------------------------------------
__global__ void __launch_bounds__(256) gemm_lse_kernel() {
    extern __shared__ float sm[];
    float* As     = sm;                              // [128][LDSW]
    float* Bs     = sm + BM * LDSW;                  // 2 stages of [128][LDSW]
    float* rowAcc = sm + BM * LDSW + 2 * BN * LDSW;  // [128]

    const int t     = threadIdx.x;
    const int lane  = t & 31;
    const int warp  = t >> 5;
    const int group = lane >> 2;   // 0..7
    const int tig   = lane & 3;    // 0..3
    const int warpM = warp >> 2;   // 0..1
    const int warpN = warp & 3;    // 0..3

    if (t < BM) rowAcc[t] = 0.0f;

    const float* Ag = g_an + (size_t)blockIdx.x * BM * DD;

    // ---- async load: A tile + B tile 0 (group 0) ----
    {
        uint32_t sA = (uint32_t)__cvta_generic_to_shared(As);
        uint32_t sB = (uint32_t)__cvta_generic_to_shared(Bs);
        #pragma unroll
        for (int c = 0; c < 16; c++) {
            int linear = c * 256 + t;        // 4096 float4 chunks
            int row  = linear >> 5;          // 0..127
            int col4 = linear & 31;          // 0..31
            CP_ASYNC16(sA + (row * LDSW + col4 * 4) * 4, Ag + row * DD + col4 * 4);
        }
        #pragma unroll
        for (int c = 0; c < 16; c++) {
            int linear = c * 256 + t;
            int row  = linear >> 5;
            int col4 = linear & 31;
            CP_ASYNC16(sB + (row * LDSW + col4 * 4) * 4, g_pn + row * DD + col4 * 4);
        }
        CP_COMMIT();
    }

    float rs[4][2];
    #pragma unroll
    for (int mi = 0; mi < 4; mi++) { rs[mi][0] = 0.0f; rs[mi][1] = 0.0f; }

    const float* pA0 = As + (warpM * 64 + group) * LDSW + tig;

    for (int jt = 0; jt < NT; jt++) {
        __syncthreads();  // stage (jt+1)&1 readers (iter jt-1) are done

        // prefetch B(jt+1)
        if (jt + 1 < NT) {
            const float* Bg = g_pn + (size_t)(jt + 1) * BN * DD;
            uint32_t sB = (uint32_t)__cvta_generic_to_shared(
                Bs + ((jt + 1) & 1) * BN * LDSW);
            #pragma unroll
            for (int c = 0; c < 16; c++) {
                int linear = c * 256 + t;
                int row  = linear >> 5;
                int col4 = linear & 31;
                CP_ASYNC16(sB + (row * LDSW + col4 * 4) * 4, Bg + row * DD + col4 * 4);
            }
        }
        CP_COMMIT();
        CP_WAIT1();       // group for stage jt complete
        __syncthreads();

        const float* Bcur = Bs + (jt & 1) * BN * LDSW;
        const float* pB0  = Bcur + (warpN * 32 + group) * LDSW + tig;

        float acc[4][4][4];
        #pragma unroll
        for (int mi = 0; mi < 4; mi++)
            #pragma unroll
            for (int ni = 0; ni < 4; ni++)
                #pragma unroll
                for (int r = 0; r < 4; r++) acc[mi][ni][r] = 0.0f;

        #pragma unroll 4
        for (int kk = 0; kk < DD; kk += 8) {
            uint32_t a[4][4], b[4][2];
            #pragma unroll
            for (int mi = 0; mi < 4; mi++) {
                const float* p = pA0 + mi * 16 * LDSW + kk;
                a[mi][0] = __float_as_uint(p[0]);
                a[mi][1] = __float_as_uint(p[8 * LDSW]);
                a[mi][2] = __float_as_uint(p[4]);
                a[mi][3] = __float_as_uint(p[8 * LDSW + 4]);
            }
            #pragma unroll
            for (int ni = 0; ni < 4; ni++) {
                const float* p = pB0 + ni * 8 * LDSW + kk;
                b[ni][0] = __float_as_uint(p[0]);
                b[ni][1] = __float_as_uint(p[4]);
            }
            #pragma unroll
            for (int mi = 0; mi < 4; mi++)
                #pragma unroll
                for (int ni = 0; ni < 4; ni++)
                    mma_tf32(acc[mi][ni], a[mi], b[ni]);
        }

        // fused epilogue: exp((d-1)/T) = 2^(d*C2 - C2)  -> 1 FMA + 1 ex2 each
        #pragma unroll
        for (int mi = 0; mi < 4; mi++) {
            float s0 = 0.0f, s1 = 0.0f;
            #pragma unroll
            for (int ni = 0; ni < 4; ni++) {
                s0 += ex2(fmaf(acc[mi][ni][0], C2EXP, -C2EXP))
                    + ex2(fmaf(acc[mi][ni][1], C2EXP, -C2EXP));
                s1 += ex2(fmaf(acc[mi][ni][2], C2EXP, -C2EXP))
                    + ex2(fmaf(acc[mi][ni][3], C2EXP, -C2EXP));
            }
            rs[mi][0] += s0;
            rs[mi][1] += s1;
        }
    }

    // ---- reduce rowsums: across tid_in_group, then across the 4 N-warps ----
    #pragma unroll
    for (int mi = 0; mi < 4; mi++) {
        float r0 = rs[mi][0], r1 = rs[mi][1];
        r0 += __shfl_xor_sync(0xFFFFFFFFu, r0, 1);
        r0 += __shfl_xor_sync(0xFFFFFFFFu, r0, 2);
        r1 += __shfl_xor_sync(0xFFFFFFFFu, r1, 1);
        r1 += __shfl_xor_sync(0xFFFFFFFFu, r1, 2);
        if (tig == 0) {
            atomicAdd(&rowAcc[warpM * 64 + mi * 16 + group],     r0);
            atomicAdd(&rowAcc[warpM * 64 + mi * 16 + group + 8], r1);
        }
    }
    __syncthreads();
    if (t < BM) g_rows[blockIdx.x * BM + t] = rowAcc[t];
}

// ---------------------------------------------------------------------------
// K3: loss = mean(log(rowsum) + 1/T - diag)
// ---------------------------------------------------------------------------
__global__ void __launch_bounds__(256) finalize_kernel(float* __restrict__ out) {
    __shared__ float red[256];
    float s = 0.0f;
    for (int i = threadIdx.x; i < NN; i += 256)
        s += logf(g_rows[i]) + INV_T - g_diag[i];
    red[threadIdx.x] = s;
    __syncthreads();
    #pragma unroll
    for (int o = 128; o > 0; o >>= 1) {
        if (threadIdx.x < o) red[threadIdx.x] += red[threadIdx.x + o];
        __syncthreads();
    }
    if (threadIdx.x == 0) out[0] = red[0] * (1.0f / NN);
}

// ---------------------------------------------------------------------------
extern "C" void kernel_launch(void* const* d_in, const int* in_sizes, int n_in,
                              void* d_out, int out_size) {
    const float* A = (const float*)d_in[0];   // anchors   [N, D]
    const float* P = (const float*)d_in[1];   // positives [N, D]
    float* out = (float*)d_out;

    normalize_kernel<<<NN / 8, 256>>>(A, P);

    const int smem = (BM * LDSW + 2 * BN * LDSW + BM) * (int)sizeof(float);
    cudaFuncSetAttribute(gemm_lse_kernel,
                         cudaFuncAttributeMaxDynamicSharedMemorySize, smem);
    gemm_lse_kernel<<<NN / BM, 256, smem>>>();

    finalize_kernel<<<1, 256>>>(out);
}

// round 14
// speedup vs baseline: 1.8374x; 1.8374x over previous
#include <cuda_runtime.h>
#include <cuda_bf16.h>
#include <cstdint>

// InfoNCE loss, N=16384, D=128, T=0.07
//   K1: normalize (fp32), exact diag, store bf16(rn) normalized vectors
//   K2: 128x128-tile NT-GEMM, mma.sync m16n8k16 bf16 (fp32 accum), fused
//       streaming sum of exp((dot-1)/T) per row   [logits <= 1/T since cos<=1]
//   K3: loss = mean(log(rowsum) + 1/T - diag)

#define NN 16384
#define DD 128
#define INV_T 14.285714285714286f
#define C2EXP 20.6108932233901f      // INV_T/ln2:  exp((d-1)/T) = 2^(d*C2 - C2)

#define BM 128
#define BN 128
#define LDSH 136                     // bf16 elems per smem row (128 + 8 pad -> CF banks)
#define NT (NN / BN)

__device__ unsigned short g_an[NN * DD];   // bf16 bits
__device__ unsigned short g_pn[NN * DD];   // bf16 bits
__device__ float g_diag[NN];
__device__ float g_rows[NN];

// ---------------------------------------------------------------------------
__device__ __forceinline__ float ex2(float x) {
    float y;
    asm("ex2.approx.ftz.f32 %0, %1;" : "=f"(y) : "f"(x));
    return y;
}

__device__ __forceinline__ uint32_t packbf(float lo, float hi) {
    __nv_bfloat162 h = __floats2bfloat162_rn(lo, hi);   // x=lo (low half), y=hi
    return *reinterpret_cast<uint32_t*>(&h);
}

#define CP_ASYNC16(dst_u32, src_ptr) \
    asm volatile("cp.async.cg.shared.global [%0], [%1], 16;" :: "r"(dst_u32), "l"(src_ptr))
#define CP_COMMIT() asm volatile("cp.async.commit_group;")
#define CP_WAIT1()  asm volatile("cp.async.wait_group 1;")

__device__ __forceinline__ void mma_bf16(float c[4], const uint32_t a[4],
                                         const uint32_t b[2]) {
    asm volatile(
        "mma.sync.aligned.m16n8k16.row.col.f32.bf16.bf16.f32 "
        "{%0,%1,%2,%3}, {%4,%5,%6,%7}, {%8,%9}, {%0,%1,%2,%3};\n"
        : "+f"(c[0]), "+f"(c[1]), "+f"(c[2]), "+f"(c[3])
        : "r"(a[0]), "r"(a[1]), "r"(a[2]), "r"(a[3]), "r"(b[0]), "r"(b[1]));
}

// ---------------------------------------------------------------------------
// K1: normalize + exact fp32 diagonal; store bf16(rn).
// ---------------------------------------------------------------------------
__global__ void __launch_bounds__(256) normalize_kernel(
    const float* __restrict__ A, const float* __restrict__ P) {
    int warp = threadIdx.x >> 5;
    int lane = threadIdx.x & 31;
    int row  = blockIdx.x * 8 + warp;

    float4 a = ((const float4*)(A + (size_t)row * DD))[lane];
    float4 p = ((const float4*)(P + (size_t)row * DD))[lane];

    float sa = a.x * a.x + a.y * a.y + a.z * a.z + a.w * a.w;
    float sp = p.x * p.x + p.y * p.y + p.z * p.z + p.w * p.w;
    #pragma unroll
    for (int o = 16; o > 0; o >>= 1) {
        sa += __shfl_xor_sync(0xFFFFFFFFu, sa, o);
        sp += __shfl_xor_sync(0xFFFFFFFFu, sp, o);
    }
    float ra = 1.0f / fmaxf(sqrtf(sa), 1e-12f);
    float rp = 1.0f / fmaxf(sqrtf(sp), 1e-12f);

    a.x *= ra; a.y *= ra; a.z *= ra; a.w *= ra;
    p.x *= rp; p.y *= rp; p.z *= rp; p.w *= rp;

    // exact fp32 diagonal BEFORE bf16 rounding
    float dot = a.x * p.x + a.y * p.y + a.z * p.z + a.w * p.w;
    #pragma unroll
    for (int o = 16; o > 0; o >>= 1)
        dot += __shfl_xor_sync(0xFFFFFFFFu, dot, o);
    if (lane == 0) g_diag[row] = dot * INV_T;

    uint2 pa = make_uint2(packbf(a.x, a.y), packbf(a.z, a.w));
    uint2 pp = make_uint2(packbf(p.x, p.y), packbf(p.z, p.w));
    ((uint2*)g_an)[(size_t)row * (DD / 4) + lane] = pa;
    ((uint2*)g_pn)[(size_t)row * (DD / 4) + lane] = pp;
}

// ---------------------------------------------------------------------------
// K2: bf16 tensor-core GEMM + fused streaming exp-sum.
// 8 warps, warp grid 2(M) x 4(N); warp tile 64x32.
// Tiles [row][k] bf16, stride LDSH=136: fragment LDS.32 (k-pairs) are CF.
// A resident; B double-buffered via cp.async (bf16 source).
// ---------------------------------------------------------------------------
__global__ void __launch_bounds__(256) gemm_lse_kernel() {
    extern __shared__ unsigned short smu[];
    unsigned short* As = smu;                      // [128][LDSH]
    unsigned short* Bs = smu + BM * LDSH;          // 2 stages of [128][LDSH]
    float* rowAcc = (float*)(smu + BM * LDSH + 2 * BN * LDSH);  // [128]

    const int t     = threadIdx.x;
    const int lane  = t & 31;
    const int warp  = t >> 5;
    const int group = lane >> 2;   // 0..7
    const int tig   = lane & 3;    // 0..3
    const int warpM = warp >> 2;   // 0..1
    const int warpN = warp & 3;    // 0..3

    if (t < BM) rowAcc[t] = 0.0f;

    const unsigned short* Ag = g_an + (size_t)blockIdx.x * BM * DD;

    // ---- async load: A tile + B tile 0. 2048 16B-chunks each (8/thread) ----
    {
        uint32_t sA = (uint32_t)__cvta_generic_to_shared(As);
        uint32_t sB = (uint32_t)__cvta_generic_to_shared(Bs);
        #pragma unroll
        for (int c = 0; c < 8; c++) {
            int linear = c * 256 + t;
            int row = linear >> 4;       // 0..127
            int ch  = linear & 15;       // 16B chunk (8 bf16)
            CP_ASYNC16(sA + (row * LDSH + ch * 8) * 2, Ag + row * DD + ch * 8);
        }
        #pragma unroll
        for (int c = 0; c < 8; c++) {
            int linear = c * 256 + t;
            int row = linear >> 4;
            int ch  = linear & 15;
            CP_ASYNC16(sB + (row * LDSH + ch * 8) * 2, g_pn + row * DD + ch * 8);
        }
        CP_COMMIT();
    }

    float rs[4][2];
    #pragma unroll
    for (int mi = 0; mi < 4; mi++) { rs[mi][0] = 0.0f; rs[mi][1] = 0.0f; }

    for (int jt = 0; jt < NT; jt++) {
        __syncthreads();   // prior readers of the stage we overwrite are done

        if (jt + 1 < NT) {
            const unsigned short* Bg = g_pn + (size_t)(jt + 1) * BN * DD;
            uint32_t sB = (uint32_t)__cvta_generic_to_shared(
                Bs + ((jt + 1) & 1) * BN * LDSH);
            #pragma unroll
            for (int c = 0; c < 8; c++) {
                int linear = c * 256 + t;
                int row = linear >> 4;
                int ch  = linear & 15;
                CP_ASYNC16(sB + (row * LDSH + ch * 8) * 2, Bg + row * DD + ch * 8);
            }
        }
        CP_COMMIT();
        CP_WAIT1();        // stage jt complete
        __syncthreads();

        const unsigned short* Bcur = Bs + (jt & 1) * BN * LDSH;

        float acc[4][4][4];
        #pragma unroll
        for (int mi = 0; mi < 4; mi++)
            #pragma unroll
            for (int ni = 0; ni < 4; ni++)
                #pragma unroll
                for (int r = 0; r < 4; r++) acc[mi][ni][r] = 0.0f;

        #pragma unroll
        for (int ks = 0; ks < 8; ks++) {
            const int kk = ks * 16;
            uint32_t a[4][4], b[4][2];
            #pragma unroll
            for (int mi = 0; mi < 4; mi++) {
                int base = (warpM * 64 + mi * 16 + group) * LDSH + kk + 2 * tig;
                a[mi][0] = *(const uint32_t*)(As + base);
                a[mi][1] = *(const uint32_t*)(As + base + 8 * LDSH);
                a[mi][2] = *(const uint32_t*)(As + base + 8);
                a[mi][3] = *(const uint32_t*)(As + base + 8 * LDSH + 8);
            }
            #pragma unroll
            for (int ni = 0; ni < 4; ni++) {
                int nb = (warpN * 32 + ni * 8 + group) * LDSH + kk + 2 * tig;
                b[ni][0] = *(const uint32_t*)(Bcur + nb);
                b[ni][1] = *(const uint32_t*)(Bcur + nb + 8);
            }
            #pragma unroll
            for (int mi = 0; mi < 4; mi++)
                #pragma unroll
                for (int ni = 0; ni < 4; ni++)
                    mma_bf16(acc[mi][ni], a[mi], b[ni]);
        }

        // fused epilogue: exp((d-1)/T) = 2^(d*C2 - C2) -> 1 FMA + 1 ex2 each
        #pragma unroll
        for (int mi = 0; mi < 4; mi++) {
            float s0 = 0.0f, s1 = 0.0f;
            #pragma unroll
            for (int ni = 0; ni < 4; ni++) {
                s0 += ex2(fmaf(acc[mi][ni][0], C2EXP, -C2EXP))
                    + ex2(fmaf(acc[mi][ni][1], C2EXP, -C2EXP));
                s1 += ex2(fmaf(acc[mi][ni][2], C2EXP, -C2EXP))
                    + ex2(fmaf(acc[mi][ni][3], C2EXP, -C2EXP));
            }
            rs[mi][0] += s0;
            rs[mi][1] += s1;
        }
    }

    // ---- reduce: across tig (shfl), then across the 4 N-warps (smem atomics)
    #pragma unroll
    for (int mi = 0; mi < 4; mi++) {
        float r0 = rs[mi][0], r1 = rs[mi][1];
        r0 += __shfl_xor_sync(0xFFFFFFFFu, r0, 1);
        r0 += __shfl_xor_sync(0xFFFFFFFFu, r0, 2);
        r1 += __shfl_xor_sync(0xFFFFFFFFu, r1, 1);
        r1 += __shfl_xor_sync(0xFFFFFFFFu, r1, 2);
        if (tig == 0) {
            atomicAdd(&rowAcc[warpM * 64 + mi * 16 + group],     r0);
            atomicAdd(&rowAcc[warpM * 64 + mi * 16 + group + 8], r1);
        }
    }
    __syncthreads();
    if (t < BM) g_rows[blockIdx.x * BM + t] = rowAcc[t];
}

// ---------------------------------------------------------------------------
// K3: loss = mean(log(rowsum) + 1/T - diag)
// ---------------------------------------------------------------------------
__global__ void __launch_bounds__(256) finalize_kernel(float* __restrict__ out) {
    __shared__ float red[256];
    float s = 0.0f;
    for (int i = threadIdx.x; i < NN; i += 256)
        s += logf(g_rows[i]) + INV_T - g_diag[i];
    red[threadIdx.x] = s;
    __syncthreads();
    #pragma unroll
    for (int o = 128; o > 0; o >>= 1) {
        if (threadIdx.x < o) red[threadIdx.x] += red[threadIdx.x + o];
        __syncthreads();
    }
    if (threadIdx.x == 0) out[0] = red[0] * (1.0f / NN);
}

// ---------------------------------------------------------------------------
extern "C" void kernel_launch(void* const* d_in, const int* in_sizes, int n_in,
                              void* d_out, int out_size) {
    const float* A = (const float*)d_in[0];   // anchors   [N, D]
    const float* P = (const float*)d_in[1];   // positives [N, D]
    float* out = (float*)d_out;

    normalize_kernel<<<NN / 8, 256>>>(A, P);

    const int smem = (BM * LDSH + 2 * BN * LDSH) * 2 + BM * 4;  // 104,960 B
    cudaFuncSetAttribute(gemm_lse_kernel,
                         cudaFuncAttributeMaxDynamicSharedMemorySize, smem);
    gemm_lse_kernel<<<NN / BM, 256, smem>>>();

    finalize_kernel<<<1, 256>>>(out);
}